// round 7
// baseline (speedup 1.0000x reference)
#include <cuda_runtime.h>
#include <math.h>

// ---------------- problem constants ----------------
#define B_    4
#define S_    2048
#define DIM_  1024
#define NH_   8
#define DH_   128
#define CS_   16
#define NS_   128
#define BH_   (B_*NH_)        // 32
#define NCHUNK (BH_*NS_)      // 4096
#define ET_   32              // e-tile width in fused kernel
#define EPS_    1e-6f
#define LN_EPS_ 1e-5f
#define NEG_   -1e30f

typedef unsigned long long ull;

// ---------------- f32x2 packed helpers (sm_103a) ----------------
__device__ __forceinline__ ull pk2(float lo, float hi) {
    ull r; asm("mov.b64 %0, {%1, %2};" : "=l"(r) : "f"(lo), "f"(hi)); return r;
}
__device__ __forceinline__ ull ffma2(ull a, ull b, ull c) {
    ull d; asm("fma.rn.f32x2 %0, %1, %2, %3;" : "=l"(d) : "l"(a), "l"(b), "l"(c)); return d;
}
__device__ __forceinline__ ull fmul2(ull a, ull b) {
    ull d; asm("mul.rn.f32x2 %0, %1, %2;" : "=l"(d) : "l"(a), "l"(b)); return d;
}
__device__ __forceinline__ void upk2(ull v, float& lo, float& hi) {
    asm("mov.b64 {%0, %1}, %2;" : "=f"(lo), "=f"(hi) : "l"(v));
}

// ---------------- scratch (device globals; no allocation) ----------------
__device__ float g_ig   [BH_*S_];
__device__ float g_fg   [BH_*S_];
__device__ float g_lfacc[BH_*S_];
__device__ float g_gexp [BH_*S_];
__device__ float g_mp   [NCHUNK];
__device__ float g_a    [NCHUNK];
__device__ float g_b    [NCHUNK];
__device__ float g_E    [NCHUNK*CS_*CS_]; // unnormalized E per chunk (16x16)
__device__ float g_qs   [NCHUNK*CS_];     // decay*scale per (chunk,c)
__device__ float g_esum [NCHUNK*CS_];     // row sums of E
__device__ float g_expns[NCHUNK*CS_];     // exp(-stab) per (chunk,c)

// ============================================================
// K1: gates.
// ============================================================
#define K1_T 8
__global__ __launch_bounds__(256) void k_gates(
    const float* __restrict__ q, const float* __restrict__ k,
    const float* __restrict__ v, const float* __restrict__ Wi,
    const float* __restrict__ bi, const float* __restrict__ Wf,
    const float* __restrict__ bf)
{
    __shared__ float sg[K1_T][1024];
    int tid  = threadIdx.x;
    int base = blockIdx.x * K1_T;
    int w    = tid >> 5;
    int lane = tid & 31;
    const float* wi = Wi + w*3072;
    const float* wf = Wf + w*3072;

    float acc_i[K1_T], acc_f[K1_T];
#pragma unroll
    for (int t = 0; t < K1_T; t++) { acc_i[t] = 0.f; acc_f[t] = 0.f; }

    for (int seg = 0; seg < 3; seg++) {
        const float* src = (seg == 0) ? q : (seg == 1) ? k : v;
        for (int r = tid; r < K1_T*256; r += 256) {
            int t = r >> 8, d4 = r & 255;
            ((float4*)sg[t])[d4] =
                ((const float4*)(src + (size_t)(base + t)*1024))[d4];
        }
        __syncthreads();
        const float* wis = wi + seg*1024;
        const float* wfs = wf + seg*1024;
#pragma unroll 2
        for (int kk = lane*4; kk < 1024; kk += 128) {
            float4 w4i = *(const float4*)&wis[kk];
            float4 w4f = *(const float4*)&wfs[kk];
#pragma unroll
            for (int t = 0; t < K1_T; t++) {
                float4 g4 = *(const float4*)&sg[t][kk];
                acc_i[t] = fmaf(g4.x, w4i.x, acc_i[t]);
                acc_i[t] = fmaf(g4.y, w4i.y, acc_i[t]);
                acc_i[t] = fmaf(g4.z, w4i.z, acc_i[t]);
                acc_i[t] = fmaf(g4.w, w4i.w, acc_i[t]);
                acc_f[t] = fmaf(g4.x, w4f.x, acc_f[t]);
                acc_f[t] = fmaf(g4.y, w4f.y, acc_f[t]);
                acc_f[t] = fmaf(g4.z, w4f.z, acc_f[t]);
                acc_f[t] = fmaf(g4.w, w4f.w, acc_f[t]);
            }
        }
        __syncthreads();
    }
#pragma unroll
    for (int t = 0; t < K1_T; t++) {
#pragma unroll
        for (int off = 16; off; off >>= 1) {
            acc_i[t] += __shfl_xor_sync(0xffffffffu, acc_i[t], off);
            acc_f[t] += __shfl_xor_sync(0xffffffffu, acc_f[t], off);
        }
    }
    if (lane == 0) {
        float biv = bi[w], bfv = bf[w];
#pragma unroll
        for (int t = 0; t < K1_T; t++) {
            int bs = base + t;
            int b = bs >> 11, s = bs & 2047;
            int idx = (b*NH_ + w)*S_ + s;
            g_ig[idx] = acc_i[t] + biv;
            g_fg[idx] = acc_f[t] + bfv;
        }
    }
}

// ============================================================
// K2: per-bh prep: logsigmoid cumsum, gexp, (a,b,mp) max-plus scan.
// ============================================================
__global__ __launch_bounds__(128) void k_prep(float* __restrict__ ml_out)
{
    __shared__ float wLs[4], wMs[4];
    int bh = blockIdx.x;
    int n  = threadIdx.x;
    int lane = n & 31, wid = n >> 5;
    int base = bh*S_ + n*16;

    float fg[16], ig[16];
#pragma unroll
    for (int i = 0; i < 4; i++) {
        float4 f4 = *(const float4*)&g_fg[base + i*4];
        float4 i4 = *(const float4*)&g_ig[base + i*4];
        fg[i*4+0]=f4.x; fg[i*4+1]=f4.y; fg[i*4+2]=f4.z; fg[i*4+3]=f4.w;
        ig[i*4+0]=i4.x; ig[i*4+1]=i4.y; ig[i*4+2]=i4.z; ig[i*4+3]=i4.w;
    }
    float lfacc[16];
    float acc = 0.f;
#pragma unroll
    for (int c = 0; c < 16; c++) {
        float f = fg[c];
        float lf = fminf(f, 0.f) - log1pf(expf(-fabsf(f)));
        acc += lf;
        lfacc[c] = acc;
    }
    float lfl = lfacc[15];
    float lg[16];
    float mloc = NEG_;
#pragma unroll
    for (int c = 0; c < 16; c++) {
        lg[c] = ig[c] - lfacc[c] + lfl;
        mloc = fmaxf(mloc, lg[c]);
    }
#pragma unroll
    for (int i = 0; i < 4; i++) {
        float4 a4, g4;
        a4.x=lfacc[i*4+0]; a4.y=lfacc[i*4+1]; a4.z=lfacc[i*4+2]; a4.w=lfacc[i*4+3];
        g4.x=expf(lg[i*4+0]-mloc); g4.y=expf(lg[i*4+1]-mloc);
        g4.z=expf(lg[i*4+2]-mloc); g4.w=expf(lg[i*4+3]-mloc);
        *(float4*)&g_lfacc[base + i*4] = a4;
        *(float4*)&g_gexp [base + i*4] = g4;
    }

    float L = lfl, M = mloc;
#pragma unroll
    for (int off = 1; off < 32; off <<= 1) {
        float Lp = __shfl_up_sync(0xffffffffu, L, off);
        float Mp = __shfl_up_sync(0xffffffffu, M, off);
        if (lane >= off) { M = fmaxf(Mp + L, M); L = Lp + L; }
    }
    if (lane == 31) { wLs[wid] = L; wMs[wid] = M; }
    __syncthreads();
    float PL = 0.f, PM = NEG_;
#pragma unroll
    for (int ww = 0; ww < 4; ww++) {
        if (ww < wid) { PM = fmaxf(PM + wLs[ww], wMs[ww]); PL += wLs[ww]; }
    }
    float Lex_w = __shfl_up_sync(0xffffffffu, L, 1);
    float Mex_w = __shfl_up_sync(0xffffffffu, M, 1);
    if (lane == 0) { Lex_w = 0.f; Mex_w = NEG_; }
    float Lex = PL + Lex_w;
    float Mex = fmaxf(PM + Lex_w, Mex_w);
    float mp = fmaxf(Lex, Mex);
    float Linc = PL + L;
    float Minc = fmaxf(PM + L, M);
    float m = fmaxf(Linc, Minc);

    int idx = bh*NS_ + n;
    g_a [idx] = expf(lfl + mp - m);
    g_b [idx] = expf(mloc - m);
    g_mp[idx] = mp;
    if (n == NS_-1) ml_out[bh] = m;
}

// ============================================================
// K3: Phase A per chunk: unnormalized E, Esum, decay, exp(-stab).
// ============================================================
#define PAD 129
__global__ __launch_bounds__(128) void k_phaseA(
    const float* __restrict__ qin, const float* __restrict__ kin)
{
    __shared__ float sq [CS_][PAD];
    __shared__ float sk [CS_][PAD];
    __shared__ float slf[CS_], sig[CS_];
    __shared__ float smp;

    int chunk = blockIdx.x;
    int bh = chunk >> 7, n = chunk & 127;
    int b = bh >> 3, h = bh & 7;
    int tid = threadIdx.x;
    const float scale = 0.08838834764831845f; // 1/sqrt(128)

    for (int r = tid; r < CS_*DH_; r += 128) {
        int c = r >> 7, d = r & 127;
        size_t gidx = (size_t)(b*S_ + n*16 + c)*DIM_ + h*DH_ + d;
        sq[c][d] = qin[gidx] * scale;
        sk[c][d] = kin[gidx];
    }
    if (tid < 16) {
        slf[tid] = g_lfacc[bh*S_ + n*16 + tid];
        sig[tid] = g_ig  [bh*S_ + n*16 + tid];
    }
    if (tid == 0) smp = g_mp[chunk];
    __syncthreads();

    int c  = tid >> 3;
    int jj = tid & 7;
    int j0 = 2*jj, j1 = 2*jj + 1;
    float qk0 = 0.f, qk1 = 0.f;
#pragma unroll 4
    for (int d = 0; d < DH_; d++) {
        float qv = sq[c][d];
        qk0 = fmaf(qv, sk[j0][d], qk0);
        qk1 = fmaf(qv, sk[j1][d], qk1);
    }
    float mp  = smp;
    float lD0 = ((j0 > c) ? NEG_ : (slf[c] - slf[j0])) + sig[j0];
    float lD1 = ((j1 > c) ? NEG_ : (slf[c] - slf[j1])) + sig[j1];
    float mrow = fmaxf(lD0, lD1);
#pragma unroll
    for (int off = 4; off; off >>= 1)
        mrow = fmaxf(mrow, __shfl_xor_sync(0xffffffffu, mrow, off, 8));
    float stab  = fmaxf(mrow, mp + slf[c]);
    float decay = expf(mp + slf[c] - stab);
    float E0 = qk0 * expf(lD0 - stab);
    float E1 = qk1 * expf(lD1 - stab);
    float Esum = E0 + E1;
#pragma unroll
    for (int off = 4; off; off >>= 1)
        Esum += __shfl_xor_sync(0xffffffffu, Esum, off, 8);
    g_E[chunk*256 + c*16 + j0] = E0;
    g_E[chunk*256 + c*16 + j1] = E1;
    if (jj == 0) {
        g_qs   [chunk*16 + c] = decay * scale;
        g_esum [chunk*16 + c] = Esum;
        g_expns[chunk*16 + c] = expf(-stab);
    }
}

// ============================================================
// K4: fused scan + output (v6): single barrier per chunk,
// fully double-buffered, deferred epilogue on update warps.
//  warps 0-7 : inter partials (K-split), pn partials
//  warps 8-15: C update (d4 x e4 layout) + n-scan + epilogue(n-1)
// ============================================================
struct __align__(16) SM6 {
    float sq[2][CS_][132];
    float sk[2][CS_][132];
    float sv[2][CS_][36];
    float sE[2][CS_][17];
    float spart[2][8][CS_][36];
    float spn[2][8][CS_];
    float sC[2][DH_][ET_];
    float sn[2][DH_];
    float sgx[2][CS_];
    float sqs[2][CS_];
};

__global__ __launch_bounds__(512, 1) void k_fused6(
    const float* __restrict__ qin, const float* __restrict__ kin,
    const float* __restrict__ vin, float* __restrict__ out,
    float* __restrict__ Cl, float* __restrict__ nl)
{
    extern __shared__ char smraw[];
    SM6* sm = (SM6*)smraw;

    int et = blockIdx.x;      // 0..3
    int bh = blockIdx.y;      // 0..31
    int b = bh >> 3, h = bh & 7;
    int tid = threadIdx.x;
    int wid = tid >> 5;
    int lane = tid & 31;

    size_t rowbase = (size_t)(b*S_)*DIM_ + h*DH_;

    // zero initial state (buffer 0)
    for (int i = tid; i < DH_*ET_; i += 512) (&sm->sC[0][0][0])[i] = 0.f;
    if (tid < DH_) sm->sn[0][tid] = 0.f;

    // staging map
    int c16 = tid >> 5, l32 = tid & 31;
    // inter map (warps 0-7)
    int cgi = lane >> 3, eg = lane & 7;
    // update map (warps 8-15): lane owns d-quad x e-quad
    int utid = tid - 256;
    int dg = (utid >= 0) ? (utid >> 3) : 0;   // 0..31 -> d0 = dg*4
    int eq = utid & 7;                         // 0..7  -> e0 = eq*4
    // epilogue map (update warps): c x e-pair
    int epc = (utid >= 0) ? (utid >> 4) : 0;   // 0..15
    int epe = utid & 15;                        // 0..15

    ull Cf2[4][2];
#pragma unroll
    for (int dd = 0; dd < 4; dd++) { Cf2[dd][0] = 0ull; Cf2[dd][1] = 0ull; }
    float nlv = 0.f;

    // prefetch registers (chunk n+1 during iter n)
    float4 qr, kr, vr = make_float4(0.f,0.f,0.f,0.f);
    float cE = 0.f, cgx = 0.f, cqs = 0.f;
    // per-chunk scalar consts: cur (chunk n), nxt (chunk n+1), prev (chunk n-1)
    float a_c=0.f, b_c=0.f, qs_c=0.f, es_c=0.f, xs_c=0.f;
    float a_n=0.f, b_n=0.f, qs_n=0.f, es_n=0.f, xs_n=0.f;
    float qs_p=0.f, es_p=0.f, xs_p=0.f;

    {   // prefetch chunk 0 into regs + cur consts
        int chunk = bh*NS_;
        qr = ((const float4*)(qin + rowbase + (size_t)(c16)*DIM_))[l32];
        kr = ((const float4*)(kin + rowbase + (size_t)(c16)*DIM_))[l32];
        if (tid < 128)
            vr = ((const float4*)(vin + rowbase + (size_t)(tid>>3)*DIM_ + et*ET_))[tid & 7];
        if (tid < 256) cE = g_E[chunk*256 + tid];
        if (tid < 16) { cgx = g_gexp[bh*S_ + tid]; cqs = g_qs[chunk*16 + tid]; }
        if (utid >= 0) {
            a_c  = g_a[chunk];  b_c  = g_b[chunk];
            qs_c = g_qs[chunk*16 + epc];
            es_c = g_esum[chunk*16 + epc];
            xs_c = g_expns[chunk*16 + epc];
        }
    }

    for (int n = 0; n <= NS_; n++) {
        int p = n & 1;
        if (n < NS_) {
            // ---- stage chunk n into buffer p (pre-barrier) ----
            *(float4*)&sm->sq[p][c16][l32*4] = qr;
            *(float4*)&sm->sk[p][c16][l32*4] = kr;
            if (tid < 128) *(float4*)&sm->sv[p][tid>>3][(tid&7)*4] = vr;
            if (tid < 256) sm->sE[p][tid>>4][tid&15] = cE;
            if (tid < 16) { sm->sgx[p][tid] = cgx; sm->sqs[p][tid] = cqs; }
        }
        __syncthreads();   // the ONLY barrier per chunk

        // ---- prefetch chunk n+1 ----
        if (n + 1 < NS_) {
            int n2 = n + 1, chunk2 = bh*NS_ + n2;
            qr = ((const float4*)(qin + rowbase + (size_t)(n2*16 + c16)*DIM_))[l32];
            kr = ((const float4*)(kin + rowbase + (size_t)(n2*16 + c16)*DIM_))[l32];
            if (tid < 128)
                vr = ((const float4*)(vin + rowbase + (size_t)(n2*16 + (tid>>3))*DIM_ + et*ET_))[tid & 7];
            if (tid < 256) cE = g_E[chunk2*256 + tid];
            if (tid < 16) { cgx = g_gexp[bh*S_ + n2*16 + tid]; cqs = g_qs[chunk2*16 + tid]; }
            if (utid >= 0) {
                a_n  = g_a[chunk2];  b_n  = g_b[chunk2];
                qs_n = g_qs[chunk2*16 + epc];
                es_n = g_esum[chunk2*16 + epc];
                xs_n = g_expns[chunk2*16 + epc];
            }
        }

        if (tid < 256) {
            if (n < NS_) {
                // ---- inter: K-split q@Cp + pn + E@v -> spart[p], spn[p] ----
                ull acc[4][2];
                float pnp[4];
#pragma unroll
                for (int i = 0; i < 4; i++) { acc[i][0] = 0ull; acc[i][1] = 0ull; pnp[i] = 0.f; }
                int k0 = wid * 16;
#pragma unroll
                for (int kk4 = 0; kk4 < 4; kk4++) {
                    int kb = k0 + kk4*4;
                    float4 qreg[4];
#pragma unroll
                    for (int i = 0; i < 4; i++)
                        qreg[i] = *(const float4*)&sm->sq[p][cgi + 4*i][kb];
                    float4 sn4 = *(const float4*)&sm->sn[p][kb];
#pragma unroll
                    for (int j = 0; j < 4; j++) {
                        ulonglong2 c2 = *(const ulonglong2*)&sm->sC[p][kb + j][eg*4];
                        float snv = ((const float*)&sn4)[j];
#pragma unroll
                        for (int i = 0; i < 4; i++) {
                            float qv = ((const float*)&qreg[i])[j];
                            ull q2 = pk2(qv, qv);
                            acc[i][0] = ffma2(q2, c2.x, acc[i][0]);
                            acc[i][1] = ffma2(q2, c2.y, acc[i][1]);
                            pnp[i] = fmaf(qv, snv, pnp[i]);
                        }
                    }
                }
#pragma unroll
                for (int i = 0; i < 4; i++) {
                    float qsv = sm->sqs[p][cgi + 4*i];
                    ull q2 = pk2(qsv, qsv);
                    acc[i][0] = fmul2(acc[i][0], q2);
                    acc[i][1] = fmul2(acc[i][1], q2);
                }
#pragma unroll
                for (int rr = 0; rr < 2; rr++) {
                    int r = wid*2 + rr;
                    ulonglong2 v2 = *(const ulonglong2*)&sm->sv[p][r][eg*4];
#pragma unroll
                    for (int i = 0; i < 4; i++) {
                        float ev = sm->sE[p][cgi + 4*i][r];
                        ull e2 = pk2(ev, ev);
                        acc[i][0] = ffma2(e2, v2.x, acc[i][0]);
                        acc[i][1] = ffma2(e2, v2.y, acc[i][1]);
                    }
                }
#pragma unroll
                for (int i = 0; i < 4; i++) {
                    ulonglong2 st; st.x = acc[i][0]; st.y = acc[i][1];
                    *(ulonglong2*)&sm->spart[p][wid][cgi + 4*i][eg*4] = st;
                }
                if (eg == 0) {
#pragma unroll
                    for (int i = 0; i < 4; i++) sm->spn[p][wid][cgi + 4*i] = pnp[i];
                }
            }
        } else {
            if (n < NS_) {
                // ---- update: Cf = a*Cf + b*k^T(v*gexp), d4xe4 layout ----
                float sgr[16];
#pragma unroll
                for (int i = 0; i < 4; i++) {
                    float4 g4 = *(const float4*)&sm->sgx[p][i*4];
                    sgr[i*4+0]=g4.x; sgr[i*4+1]=g4.y; sgr[i*4+2]=g4.z; sgr[i*4+3]=g4.w;
                }
                ull acc2[4][2];
#pragma unroll
                for (int dd = 0; dd < 4; dd++) { acc2[dd][0] = 0ull; acc2[dd][1] = 0ull; }
#pragma unroll
                for (int c = 0; c < 16; c++) {
                    float4 v4 = *(const float4*)&sm->sv[p][c][eq*4];
                    float gv = sgr[c];
                    ull vg0 = pk2(v4.x * gv, v4.y * gv);
                    ull vg1 = pk2(v4.z * gv, v4.w * gv);
                    float4 k4 = *(const float4*)&sm->sk[p][c][dg*4];
                    acc2[0][0] = ffma2(pk2(k4.x, k4.x), vg0, acc2[0][0]);
                    acc2[0][1] = ffma2(pk2(k4.x, k4.x), vg1, acc2[0][1]);
                    acc2[1][0] = ffma2(pk2(k4.y, k4.y), vg0, acc2[1][0]);
                    acc2[1][1] = ffma2(pk2(k4.y, k4.y), vg1, acc2[1][1]);
                    acc2[2][0] = ffma2(pk2(k4.z, k4.z), vg0, acc2[2][0]);
                    acc2[2][1] = ffma2(pk2(k4.z, k4.z), vg1, acc2[2][1]);
                    acc2[3][0] = ffma2(pk2(k4.w, k4.w), vg0, acc2[3][0]);
                    acc2[3][1] = ffma2(pk2(k4.w, k4.w), vg1, acc2[3][1]);
                }
                ull a2 = pk2(a_c, a_c), b2 = pk2(b_c, b_c);
#pragma unroll
                for (int dd = 0; dd < 4; dd++) {
                    Cf2[dd][0] = ffma2(Cf2[dd][0], a2, fmul2(acc2[dd][0], b2));
                    Cf2[dd][1] = ffma2(Cf2[dd][1], a2, fmul2(acc2[dd][1], b2));
                }
                // republish next-chunk state into buffer p^1
#pragma unroll
                for (int dd = 0; dd < 4; dd++) {
                    ulonglong2 st; st.x = Cf2[dd][0]; st.y = Cf2[dd][1];
                    *(ulonglong2*)&sm->sC[p^1][dg*4 + dd][eq*4] = st;
                }
                // ksum + n-scan (first 4 update warps)
                if (utid < 128) {
                    float ks = 0.f;
#pragma unroll
                    for (int c = 0; c < 16; c++)
                        ks = fmaf(sm->sk[p][c][utid], sgr[c], ks);
                    float nn = fmaf(sm->sn[p][utid], a_c, ks * b_c);
                    sm->sn[p^1][utid] = nn;
                    if (n == NS_-1) nlv = nn;
                }
            }
            if (n >= 1) {
                // ---- deferred epilogue for chunk n-1 (buffers p^1) ----
                float2 h2 = make_float2(0.f, 0.f);
#pragma unroll
                for (int w = 0; w < 8; w++) {
                    float2 pp = *(const float2*)&sm->spart[p^1][w][epc][epe*2];
                    h2.x += pp.x; h2.y += pp.y;
                }
                float pn = 0.f;
#pragma unroll
                for (int w = 0; w < 8; w++) pn += sm->spn[p^1][w][epc];
                float norm = fmaxf(fabsf(es_p + qs_p*pn), xs_p) + EPS_;
                float inv = 1.f / norm;
                h2.x *= inv; h2.y *= inv;
                *(float2*)(out + rowbase + (size_t)((n-1)*16 + epc)*DIM_ + et*ET_ + epe*2) = h2;
            }
        }

        // rotate per-chunk consts
        qs_p = qs_c; es_p = es_c; xs_p = xs_c;
        a_c = a_n; b_c = b_n; qs_c = qs_n; es_c = es_n; xs_c = xs_n;
    }

    // ---- final states ----
    if (utid >= 0) {
        size_t clb = (size_t)bh * (DH_*DH_);
#pragma unroll
        for (int dd = 0; dd < 4; dd++) {
            float lo0, hi0, lo1, hi1;
            upk2(Cf2[dd][0], lo0, hi0);
            upk2(Cf2[dd][1], lo1, hi1);
            float4 cv = make_float4(lo0, hi0, lo1, hi1);
            *(float4*)&Cl[clb + (size_t)(dg*4 + dd)*DH_ + et*ET_ + eq*4] = cv;
        }
        if (et == 0 && utid < 128) nl[bh*DH_ + utid] = nlv;
    }
}

// ============================================================
// K5: in-place layernorm over out, per (b,s,head) row of 128.
// ============================================================
__global__ __launch_bounds__(256) void k_ln(
    const float* __restrict__ lnw, const float* __restrict__ lnb,
    float* __restrict__ out)
{
    int r = blockIdx.x*8 + (threadIdx.x >> 5);
    int lane = threadIdx.x & 31;
    int bs = r >> 3, h = r & 7;
    float4* p = (float4*)(out + (size_t)bs*DIM_ + h*DH_);
    float4 x = p[lane];
    float s1 = x.x + x.y + x.z + x.w;
#pragma unroll
    for (int off = 16; off; off >>= 1)
        s1 += __shfl_xor_sync(0xffffffffu, s1, off);
    float mu = s1 * (1.f/128.f);
    float dx = x.x - mu, dy = x.y - mu, dz = x.z - mu, dw = x.w - mu;
    float s2 = dx*dx + dy*dy + dz*dz + dw*dw;
#pragma unroll
    for (int off = 16; off; off >>= 1)
        s2 += __shfl_xor_sync(0xffffffffu, s2, off);
    float rstd = rsqrtf(s2 * (1.f/128.f) + LN_EPS_);
    float4 w = ((const float4*)(lnw + h*DH_))[lane];
    float4 bb = ((const float4*)(lnb + h*DH_))[lane];
    x.x = dx*rstd*(1.f + w.x) + bb.x;
    x.y = dy*rstd*(1.f + w.y) + bb.y;
    x.z = dz*rstd*(1.f + w.z) + bb.z;
    x.w = dw*rstd*(1.f + w.w) + bb.w;
    p[lane] = x;
}

// ============================================================
extern "C" void kernel_launch(void* const* d_in, const int* in_sizes, int n_in,
                              void* d_out, int out_size)
{
    const float* q   = (const float*)d_in[0];
    const float* k   = (const float*)d_in[1];
    const float* v   = (const float*)d_in[2];
    const float* Wi  = (const float*)d_in[3];
    const float* bi  = (const float*)d_in[4];
    const float* Wf  = (const float*)d_in[5];
    const float* bf  = (const float*)d_in[6];
    const float* lnw = (const float*)d_in[7];
    const float* lnb = (const float*)d_in[8];

    float* out = (float*)d_out;
    float* Cl  = out + (size_t)B_*S_*DIM_;
    float* nl  = Cl  + (size_t)BH_*DH_*DH_;
    float* ml  = nl  + (size_t)BH_*DH_;

    cudaFuncSetAttribute(k_fused6,
        cudaFuncAttributeMaxDynamicSharedMemorySize, (int)sizeof(SM6));

    k_gates  <<< (B_*S_)/K1_T, 256 >>>(q, k, v, Wi, bi, Wf, bf);
    k_prep   <<< BH_, 128 >>>(ml);
    k_phaseA <<< NCHUNK, 128 >>>(q, k);
    dim3 gf(4, BH_);
    k_fused6 <<< gf, 512, sizeof(SM6) >>>(q, k, v, out, Cl, nl);
    k_ln     <<< (B_*S_*NH_)/8, 256 >>>(lnw, lnb, out);
}